// round 2
// baseline (speedup 1.0000x reference)
#include <cuda_runtime.h>

// Problem constants
#define BSZ 4
#define TLEN 2048
#define CDIM 1024
#define HN 16
#define HDIM 64

// Scratch (device globals; no allocation allowed)
__device__ float g_q[BSZ*HN*TLEN*HDIM];   // [B,H,T,HD]
__device__ float g_k[BSZ*HN*TLEN*HDIM];
__device__ float g_v[BSZ*HN*TLEN*HDIM];
__device__ float g_ao[BSZ*TLEN*CDIM];     // attention output [B,T,C]

// ---------------------------------------------------------------------------
// SGEMM 1: qkv = x @ w_attn, epilogue scatters into Q/K/V [B,H,T,HD]
// M=8192, N=3072, K=1024. 128x128x8 tiles, 256 threads, 8x8 per thread.
// ---------------------------------------------------------------------------
__global__ __launch_bounds__(256) void sgemm_qkv(
    const float* __restrict__ A,   // [8192,1024]
    const float* __restrict__ Bm)  // [1024,3072]
{
    const int K = 1024, N = 3072;
    __shared__ float As[8][128];   // transposed A tile
    __shared__ float Bs[8][128];

    int tid = threadIdx.x;
    int m0 = blockIdx.y * 128;
    int n0 = blockIdx.x * 128;

    int arow = tid >> 1, acol = (tid & 1) << 2;
    int brow = tid >> 5, bcol = (tid & 31) << 2;
    int ty = tid >> 4, tx = tid & 15;

    const float* Ap = A + (size_t)(m0 + arow) * K + acol;
    const float* Bp = Bm + (size_t)brow * N + n0 + bcol;

    float acc[8][8];
    #pragma unroll
    for (int i = 0; i < 8; i++)
        #pragma unroll
        for (int j = 0; j < 8; j++) acc[i][j] = 0.f;

    for (int kk = 0; kk < K; kk += 8) {
        float4 av = *(const float4*)(Ap + kk);
        float4 bv = *(const float4*)(Bp + (size_t)kk * N);
        __syncthreads();
        As[acol+0][arow] = av.x; As[acol+1][arow] = av.y;
        As[acol+2][arow] = av.z; As[acol+3][arow] = av.w;
        *(float4*)&Bs[brow][bcol] = bv;
        __syncthreads();
        #pragma unroll
        for (int k = 0; k < 8; k++) {
            float a[8], b[8];
            *(float4*)(a)     = *(const float4*)&As[k][ty*8];
            *(float4*)(a + 4) = *(const float4*)&As[k][ty*8 + 4];
            *(float4*)(b)     = *(const float4*)&Bs[k][tx*8];
            *(float4*)(b + 4) = *(const float4*)&Bs[k][tx*8 + 4];
            #pragma unroll
            for (int i = 0; i < 8; i++)
                #pragma unroll
                for (int j = 0; j < 8; j++)
                    acc[i][j] += a[i] * b[j];
        }
    }

    // Scatter epilogue: col n -> (which, h, d); row m -> (b, t)
    #pragma unroll
    for (int i = 0; i < 8; i++) {
        int m = m0 + ty*8 + i;
        int bb = m >> 11;        // / 2048
        int t  = m & 2047;
        #pragma unroll
        for (int j4 = 0; j4 < 8; j4 += 4) {
            int n = n0 + tx*8 + j4;          // aligned to 4, within one head block
            int which = n >> 10;
            int c = n & 1023;
            int h = c >> 6;
            int d = c & 63;
            float* dst = (which == 0) ? g_q : (which == 1) ? g_k : g_v;
            float4 v4 = make_float4(acc[i][j4], acc[i][j4+1], acc[i][j4+2], acc[i][j4+3]);
            *(float4*)&dst[(((size_t)(bb*HN + h))*TLEN + t)*HDIM + d] = v4;
        }
    }
}

// ---------------------------------------------------------------------------
// SGEMM 2: out = g_ao @ w_proj + bias. M=8192, N=1024, K=1024.
// NOTE: g_ao referenced directly in device code (device-global symbol is NOT
// a valid pointer on the host side).
// ---------------------------------------------------------------------------
__global__ __launch_bounds__(256) void sgemm_proj(
    const float* __restrict__ Bm,   // w_proj [1024,1024]
    const float* __restrict__ bias, // [1024]
    float* __restrict__ out)        // [8192,1024]
{
    const int K = 1024, N = 1024;
    __shared__ float As[8][128];
    __shared__ float Bs[8][128];

    const float* __restrict__ A = g_ao;   // [8192,1024], device-side address

    int tid = threadIdx.x;
    int m0 = blockIdx.y * 128;
    int n0 = blockIdx.x * 128;

    int arow = tid >> 1, acol = (tid & 1) << 2;
    int brow = tid >> 5, bcol = (tid & 31) << 2;
    int ty = tid >> 4, tx = tid & 15;

    const float* Ap = A + (size_t)(m0 + arow) * K + acol;
    const float* Bp = Bm + (size_t)brow * N + n0 + bcol;

    float acc[8][8];
    #pragma unroll
    for (int i = 0; i < 8; i++)
        #pragma unroll
        for (int j = 0; j < 8; j++) acc[i][j] = 0.f;

    for (int kk = 0; kk < K; kk += 8) {
        float4 av = *(const float4*)(Ap + kk);
        float4 bv = *(const float4*)(Bp + (size_t)kk * N);
        __syncthreads();
        As[acol+0][arow] = av.x; As[acol+1][arow] = av.y;
        As[acol+2][arow] = av.z; As[acol+3][arow] = av.w;
        *(float4*)&Bs[brow][bcol] = bv;
        __syncthreads();
        #pragma unroll
        for (int k = 0; k < 8; k++) {
            float a[8], b[8];
            *(float4*)(a)     = *(const float4*)&As[k][ty*8];
            *(float4*)(a + 4) = *(const float4*)&As[k][ty*8 + 4];
            *(float4*)(b)     = *(const float4*)&Bs[k][tx*8];
            *(float4*)(b + 4) = *(const float4*)&Bs[k][tx*8 + 4];
            #pragma unroll
            for (int i = 0; i < 8; i++)
                #pragma unroll
                for (int j = 0; j < 8; j++)
                    acc[i][j] += a[i] * b[j];
        }
    }

    #pragma unroll
    for (int i = 0; i < 8; i++) {
        int m = m0 + ty*8 + i;
        #pragma unroll
        for (int j4 = 0; j4 < 8; j4 += 4) {
            int n = n0 + tx*8 + j4;
            float4 bb = *(const float4*)&bias[n];
            float4 v4 = make_float4(acc[i][j4]   + bb.x, acc[i][j4+1] + bb.y,
                                    acc[i][j4+2] + bb.z, acc[i][j4+3] + bb.w);
            *(float4*)&out[(size_t)m * N + n] = v4;
        }
    }
}

// ---------------------------------------------------------------------------
// Flash attention, fp32, online softmax.
// Block = (qtile of 64 rows) x (one bh). 256 threads as 16x16 grid; each
// thread owns a 4x4 fragment of S/P and a 4(rows)x4(dims) fragment of O.
// Causal: only key tiles 0..qi processed; mask applied on diagonal tile only.
// ---------------------------------------------------------------------------
__global__ __launch_bounds__(256) void attn_kernel()
{
    __shared__ float Qt[64*64];    // Qt[d*64 + row]
    __shared__ float KtPs[64*64];  // Kt[d*64 + key]  /  Ps[row*64 + key]
    __shared__ float Vs[64*64];    // Vs[key*64 + d]

    int bh  = blockIdx.y;           // 0..63
    int qi  = blockIdx.x;           // 0..31
    int qm0 = qi * 64;

    const float* Qp = g_q + ((size_t)bh * TLEN + qm0) * HDIM;
    const float* Kp = g_k + (size_t)bh * TLEN * HDIM;
    const float* Vp = g_v + (size_t)bh * TLEN * HDIM;

    int tid = threadIdx.x;
    int ty = tid >> 4, tx = tid & 15;

    // Load Q tile transposed: strided gmem read -> conflict-free smem stores
    for (int i = tid; i < 1024; i += 256) {
        int row = i & 63;
        int c4 = (i >> 6) << 2;
        float4 q = *(const float4*)(Qp + row*HDIM + c4);
        Qt[(c4+0)*64 + row] = q.x; Qt[(c4+1)*64 + row] = q.y;
        Qt[(c4+2)*64 + row] = q.z; Qt[(c4+3)*64 + row] = q.w;
    }

    float O[4][4];
    float m_run[4], l_run[4];
    #pragma unroll
    for (int i = 0; i < 4; i++) {
        m_run[i] = -1e30f; l_run[i] = 0.f;
        #pragma unroll
        for (int j = 0; j < 4; j++) O[i][j] = 0.f;
    }

    const float scale = 0.125f;  // 1/sqrt(64)
    int nt = qi + 1;

    for (int jt = 0; jt < nt; jt++) {
        int k0 = jt * 64;
        __syncthreads();  // prior PV reads of KtPs/Vs complete

        // K tile transposed (strided gmem, conflict-free smem)
        for (int i = tid; i < 1024; i += 256) {
            int row = i & 63;
            int c4 = (i >> 6) << 2;
            float4 kv = *(const float4*)(Kp + (size_t)(k0 + row)*HDIM + c4);
            KtPs[(c4+0)*64 + row] = kv.x; KtPs[(c4+1)*64 + row] = kv.y;
            KtPs[(c4+2)*64 + row] = kv.z; KtPs[(c4+3)*64 + row] = kv.w;
        }
        // V tile (coalesced, conflict-free)
        for (int i = tid; i < 1024; i += 256) {
            int row = i >> 4;
            int c4 = (i & 15) << 2;
            *(float4*)&Vs[row*64 + c4] = *(const float4*)(Vp + (size_t)(k0 + row)*HDIM + c4);
        }
        __syncthreads();

        // S = Q K^T (4x4 fragment per thread)
        float s[4][4];
        #pragma unroll
        for (int i = 0; i < 4; i++)
            #pragma unroll
            for (int j = 0; j < 4; j++) s[i][j] = 0.f;

        #pragma unroll 4
        for (int d = 0; d < 64; d++) {
            float4 a4 = *(const float4*)&Qt[d*64 + ty*4];
            float4 b4 = *(const float4*)&KtPs[d*64 + tx*4];
            float a[4] = {a4.x, a4.y, a4.z, a4.w};
            float b[4] = {b4.x, b4.y, b4.z, b4.w};
            #pragma unroll
            for (int i = 0; i < 4; i++)
                #pragma unroll
                for (int j = 0; j < 4; j++)
                    s[i][j] += a[i] * b[j];
        }

        // scale + causal mask (only diagonal tile can be masked)
        if (jt == qi) {
            #pragma unroll
            for (int i = 0; i < 4; i++)
                #pragma unroll
                for (int j = 0; j < 4; j++)
                    s[i][j] = (tx*4 + j <= ty*4 + i) ? s[i][j]*scale : -1e30f;
        } else {
            #pragma unroll
            for (int i = 0; i < 4; i++)
                #pragma unroll
                for (int j = 0; j < 4; j++)
                    s[i][j] *= scale;
        }

        // online softmax update (row group = 16 threads sharing ty)
        float fac[4];
        #pragma unroll
        for (int i = 0; i < 4; i++) {
            float rmax = fmaxf(fmaxf(s[i][0], s[i][1]), fmaxf(s[i][2], s[i][3]));
            #pragma unroll
            for (int off = 8; off > 0; off >>= 1)
                rmax = fmaxf(rmax, __shfl_xor_sync(0xffffffffu, rmax, off));
            float mnew = fmaxf(m_run[i], rmax);
            float rsum = 0.f;
            #pragma unroll
            for (int j = 0; j < 4; j++) {
                s[i][j] = __expf(s[i][j] - mnew);   // p
                rsum += s[i][j];
            }
            #pragma unroll
            for (int off = 8; off > 0; off >>= 1)
                rsum += __shfl_xor_sync(0xffffffffu, rsum, off);
            fac[i] = __expf(m_run[i] - mnew);
            l_run[i] = l_run[i] * fac[i] + rsum;
            m_run[i] = mnew;
            #pragma unroll
            for (int j = 0; j < 4; j++) O[i][j] *= fac[i];
        }

        __syncthreads();  // all S reads of Kt done; reuse buffer as Ps

        // store P as Ps[row][key] (conflict-free float4 stores)
        #pragma unroll
        for (int i = 0; i < 4; i++) {
            float4 p4 = make_float4(s[i][0], s[i][1], s[i][2], s[i][3]);
            *(float4*)&KtPs[(ty*4 + i)*64 + tx*4] = p4;
        }
        __syncthreads();

        // O += P V (a: broadcast scalar, b: conflict-free float4)
        #pragma unroll 4
        for (int k = 0; k < 64; k++) {
            float4 b4 = *(const float4*)&Vs[k*64 + tx*4];
            float b[4] = {b4.x, b4.y, b4.z, b4.w};
            float a[4];
            #pragma unroll
            for (int i = 0; i < 4; i++) a[i] = KtPs[(ty*4 + i)*64 + k];
            #pragma unroll
            for (int i = 0; i < 4; i++)
                #pragma unroll
                for (int j = 0; j < 4; j++)
                    O[i][j] += a[i] * b[j];
        }
    }

    // finalize + write to [B,T,C] layout
    int b = bh >> 4, h = bh & 15;
    #pragma unroll
    for (int i = 0; i < 4; i++) {
        int t = qm0 + ty*4 + i;
        float inv = 1.0f / l_run[i];
        float4 o4 = make_float4(O[i][0]*inv, O[i][1]*inv, O[i][2]*inv, O[i][3]*inv);
        *(float4*)&g_ao[((size_t)b*TLEN + t)*CDIM + h*HDIM + tx*4] = o4;
    }
}

// ---------------------------------------------------------------------------
extern "C" void kernel_launch(void* const* d_in, const int* in_sizes, int n_in,
                              void* d_out, int out_size)
{
    const float* x      = (const float*)d_in[0];
    const float* w_attn = (const float*)d_in[1];
    const float* w_proj = (const float*)d_in[2];
    const float* b_proj = (const float*)d_in[3];
    float* out = (float*)d_out;

    dim3 g1(3072/128, 8192/128);   // (24, 64)
    sgemm_qkv<<<g1, 256>>>(x, w_attn);

    dim3 g2(TLEN/64, BSZ*HN);      // (32, 64)
    attn_kernel<<<g2, 256>>>();

    dim3 g3(1024/128, 8192/128);   // (8, 64)
    sgemm_proj<<<g3, 256>>>(w_proj, b_proj, out);
}

// round 3
// speedup vs baseline: 1.6672x; 1.6672x over previous
#include <cuda_runtime.h>
#include <cstdint>

// Problem constants
#define BSZ 4
#define TLEN 2048
#define CDIM 1024
#define HN 16
#define HDIM 64

// Scratch (device globals; no allocation allowed)
__device__ float g_q[BSZ*HN*TLEN*HDIM];   // [B,H,T,HD]  (pre-scaled by 1/8)
__device__ float g_k[BSZ*HN*TLEN*HDIM];
__device__ float g_v[BSZ*HN*TLEN*HDIM];
__device__ float g_ao[BSZ*TLEN*CDIM];     // attention output [B,T,C]

// ---------------------------------------------------------------------------
// tf32 helpers
// ---------------------------------------------------------------------------
__device__ __forceinline__ unsigned f2tf32(float x) {
    unsigned y;
    asm("cvt.rna.tf32.f32 %0, %1;" : "=r"(y) : "f"(x));
    return y;
}

__device__ __forceinline__ void mma_tf32(float c[4],
                                         unsigned a0, unsigned a1, unsigned a2, unsigned a3,
                                         unsigned b0, unsigned b1) {
    asm volatile(
        "mma.sync.aligned.m16n8k8.row.col.f32.tf32.tf32.f32 "
        "{%0,%1,%2,%3}, {%4,%5,%6,%7}, {%8,%9}, {%0,%1,%2,%3};"
        : "+f"(c[0]), "+f"(c[1]), "+f"(c[2]), "+f"(c[3])
        : "r"(a0), "r"(a1), "r"(a2), "r"(a3), "r"(b0), "r"(b1));
}

// ---------------------------------------------------------------------------
// tf32 tensor-core GEMM: C[8192 x N] = A[8192 x 1024] @ B[1024 x N]
// Block 128x128xBK16, 128 threads (4 warps), warp tile 64x64 (m16n8k8 x 4x8).
// Double-buffered smem; padded strides for conflict-free fragment LDS.
// EPI 0: scatter into g_q (x0.125) / g_k / g_v.   EPI 1: +bias -> out.
// ---------------------------------------------------------------------------
template<int N, int EPI>
__global__ __launch_bounds__(128) void gemm_tf32(
    const float* __restrict__ A,
    const float* __restrict__ Bm,
    const float* __restrict__ bias,
    float* __restrict__ out)
{
    const int K = 1024;
    __shared__ unsigned As[2][128][20];   // [m][k], pad 20: LDS banks (20g+q) distinct
    __shared__ unsigned Bs[2][16][136];   // [k][n], pad 136: LDS banks (8q+g) distinct

    const int tid  = threadIdx.x;
    const int wid  = tid >> 5;
    const int lane = tid & 31;
    const int g    = lane >> 2;     // groupID
    const int q    = lane & 3;      // threadID_in_group
    const int wm   = (wid >> 1) * 64;
    const int wn   = (wid & 1) * 64;
    const int m0   = blockIdx.y * 128;
    const int n0   = blockIdx.x * 128;

    // loader indices
    const int lar = tid >> 2, lac = (tid & 3) << 2;    // A: row lar+32i, col lac..+3
    const int lbr = tid >> 5, lbc = (tid & 31) << 2;   // B: row lbr+4i,  col lbc..+3

    float acc[4][8][4];
    #pragma unroll
    for (int mt = 0; mt < 4; mt++)
        #pragma unroll
        for (int nt = 0; nt < 8; nt++)
            #pragma unroll
            for (int c = 0; c < 4; c++) acc[mt][nt][c] = 0.f;

    float4 ra[4], rb[4];

    // prologue: load k-tile 0
    #pragma unroll
    for (int i = 0; i < 4; i++)
        ra[i] = *(const float4*)&A[(size_t)(m0 + lar + 32*i) * K + lac];
    #pragma unroll
    for (int i = 0; i < 4; i++)
        rb[i] = *(const float4*)&Bm[(size_t)(lbr + 4*i) * N + n0 + lbc];
    #pragma unroll
    for (int i = 0; i < 4; i++) {
        As[0][lar + 32*i][lac+0] = f2tf32(ra[i].x);
        As[0][lar + 32*i][lac+1] = f2tf32(ra[i].y);
        As[0][lar + 32*i][lac+2] = f2tf32(ra[i].z);
        As[0][lar + 32*i][lac+3] = f2tf32(ra[i].w);
    }
    #pragma unroll
    for (int i = 0; i < 4; i++) {
        Bs[0][lbr + 4*i][lbc+0] = f2tf32(rb[i].x);
        Bs[0][lbr + 4*i][lbc+1] = f2tf32(rb[i].y);
        Bs[0][lbr + 4*i][lbc+2] = f2tf32(rb[i].z);
        Bs[0][lbr + 4*i][lbc+3] = f2tf32(rb[i].w);
    }
    __syncthreads();

    const int NIT = K / 16;   // 64
    for (int it = 0; it < NIT; it++) {
        const int cur = it & 1;
        const int nxt = cur ^ 1;

        // issue next-tile gmem loads early
        if (it + 1 < NIT) {
            const int kk = (it + 1) * 16;
            #pragma unroll
            for (int i = 0; i < 4; i++)
                ra[i] = *(const float4*)&A[(size_t)(m0 + lar + 32*i) * K + kk + lac];
            #pragma unroll
            for (int i = 0; i < 4; i++)
                rb[i] = *(const float4*)&Bm[(size_t)(kk + lbr + 4*i) * N + n0 + lbc];
        }

        // compute on current stage: 2 k-steps of 8
        #pragma unroll
        for (int ks = 0; ks < 2; ks++) {
            const int kq = ks * 8 + q;
            unsigned af[4][4];
            #pragma unroll
            for (int mt = 0; mt < 4; mt++) {
                const int mb = wm + mt*16 + g;
                af[mt][0] = As[cur][mb    ][kq];
                af[mt][1] = As[cur][mb + 8][kq];
                af[mt][2] = As[cur][mb    ][kq + 4];
                af[mt][3] = As[cur][mb + 8][kq + 4];
            }
            unsigned bf[8][2];
            #pragma unroll
            for (int nt = 0; nt < 8; nt++) {
                const int nb = wn + nt*8 + g;
                bf[nt][0] = Bs[cur][ks*8 + q    ][nb];
                bf[nt][1] = Bs[cur][ks*8 + q + 4][nb];
            }
            #pragma unroll
            for (int mt = 0; mt < 4; mt++)
                #pragma unroll
                for (int nt = 0; nt < 8; nt++)
                    mma_tf32(acc[mt][nt], af[mt][0], af[mt][1], af[mt][2], af[mt][3],
                             bf[nt][0], bf[nt][1]);
        }

        // stage next tile
        if (it + 1 < NIT) {
            #pragma unroll
            for (int i = 0; i < 4; i++) {
                As[nxt][lar + 32*i][lac+0] = f2tf32(ra[i].x);
                As[nxt][lar + 32*i][lac+1] = f2tf32(ra[i].y);
                As[nxt][lar + 32*i][lac+2] = f2tf32(ra[i].z);
                As[nxt][lar + 32*i][lac+3] = f2tf32(ra[i].w);
            }
            #pragma unroll
            for (int i = 0; i < 4; i++) {
                Bs[nxt][lbr + 4*i][lbc+0] = f2tf32(rb[i].x);
                Bs[nxt][lbr + 4*i][lbc+1] = f2tf32(rb[i].y);
                Bs[nxt][lbr + 4*i][lbc+2] = f2tf32(rb[i].z);
                Bs[nxt][lbr + 4*i][lbc+3] = f2tf32(rb[i].w);
            }
        }
        __syncthreads();
    }

    // Epilogue: acc[mt][nt]: c0 -> (row m+g, col n+2q), c1 -> col n+2q+1,
    //                        c2 -> (row m+g+8, col n+2q), c3 -> +1.
    #pragma unroll
    for (int mt = 0; mt < 4; mt++) {
        #pragma unroll
        for (int nt = 0; nt < 8; nt++) {
            const int m = m0 + wm + mt*16 + g;
            const int n = n0 + wn + nt*8 + 2*q;
            if (EPI == 0) {
                // scatter into q/k/v [B,H,T,HD]; q pre-scaled by 1/8
                const int which = n >> 10;
                const int c = n & 1023;
                const int h = c >> 6;
                const int d = c & 63;
                float* dst = (which == 0) ? g_q : (which == 1) ? g_k : g_v;
                const float sc = (which == 0) ? 0.125f : 1.0f;
                #pragma unroll
                for (int r = 0; r < 2; r++) {
                    const int mm = m + r*8;
                    const int bb = mm >> 11;
                    const int t  = mm & 2047;
                    float2 v2 = make_float2(acc[mt][nt][r*2]   * sc,
                                            acc[mt][nt][r*2+1] * sc);
                    *(float2*)&dst[(((size_t)(bb*HN + h))*TLEN + t)*HDIM + d] = v2;
                }
            } else {
                const float2 bb = *(const float2*)&bias[n];
                #pragma unroll
                for (int r = 0; r < 2; r++) {
                    const int mm = m + r*8;
                    float2 v2 = make_float2(acc[mt][nt][r*2]   + bb.x,
                                            acc[mt][nt][r*2+1] + bb.y);
                    *(float2*)&out[(size_t)mm * N + n] = v2;
                }
            }
        }
    }
}

// ---------------------------------------------------------------------------
// Flash attention, fp32, online softmax (q pre-scaled by 1/8 in qkv epilogue).
// Block = (qtile of 64 rows) x (one bh). 256 threads as 16x16 grid.
// ---------------------------------------------------------------------------
__global__ __launch_bounds__(256) void attn_kernel()
{
    __shared__ float Qt[64*64];    // Qt[d*64 + row]
    __shared__ float KtPs[64*64];  // Kt[d*64 + key]  /  Ps[row*64 + key]
    __shared__ float Vs[64*64];    // Vs[key*64 + d]

    int bh  = blockIdx.y;           // 0..63
    int qi  = blockIdx.x;           // 0..31
    int qm0 = qi * 64;

    const float* Qp = g_q + ((size_t)bh * TLEN + qm0) * HDIM;
    const float* Kp = g_k + (size_t)bh * TLEN * HDIM;
    const float* Vp = g_v + (size_t)bh * TLEN * HDIM;

    int tid = threadIdx.x;
    int ty = tid >> 4, tx = tid & 15;

    for (int i = tid; i < 1024; i += 256) {
        int row = i & 63;
        int c4 = (i >> 6) << 2;
        float4 qv = *(const float4*)(Qp + row*HDIM + c4);
        Qt[(c4+0)*64 + row] = qv.x; Qt[(c4+1)*64 + row] = qv.y;
        Qt[(c4+2)*64 + row] = qv.z; Qt[(c4+3)*64 + row] = qv.w;
    }

    float O[4][4];
    float m_run[4], l_run[4];
    #pragma unroll
    for (int i = 0; i < 4; i++) {
        m_run[i] = -1e30f; l_run[i] = 0.f;
        #pragma unroll
        for (int j = 0; j < 4; j++) O[i][j] = 0.f;
    }

    int nt = qi + 1;

    for (int jt = 0; jt < nt; jt++) {
        int k0 = jt * 64;
        __syncthreads();

        for (int i = tid; i < 1024; i += 256) {
            int row = i & 63;
            int c4 = (i >> 6) << 2;
            float4 kv = *(const float4*)(Kp + (size_t)(k0 + row)*HDIM + c4);
            KtPs[(c4+0)*64 + row] = kv.x; KtPs[(c4+1)*64 + row] = kv.y;
            KtPs[(c4+2)*64 + row] = kv.z; KtPs[(c4+3)*64 + row] = kv.w;
        }
        for (int i = tid; i < 1024; i += 256) {
            int row = i >> 4;
            int c4 = (i & 15) << 2;
            *(float4*)&Vs[row*64 + c4] = *(const float4*)(Vp + (size_t)(k0 + row)*HDIM + c4);
        }
        __syncthreads();

        float s[4][4];
        #pragma unroll
        for (int i = 0; i < 4; i++)
            #pragma unroll
            for (int j = 0; j < 4; j++) s[i][j] = 0.f;

        #pragma unroll 4
        for (int d = 0; d < 64; d++) {
            float4 a4 = *(const float4*)&Qt[d*64 + ty*4];
            float4 b4 = *(const float4*)&KtPs[d*64 + tx*4];
            float a[4] = {a4.x, a4.y, a4.z, a4.w};
            float b[4] = {b4.x, b4.y, b4.z, b4.w};
            #pragma unroll
            for (int i = 0; i < 4; i++)
                #pragma unroll
                for (int j = 0; j < 4; j++)
                    s[i][j] += a[i] * b[j];
        }

        if (jt == qi) {
            #pragma unroll
            for (int i = 0; i < 4; i++)
                #pragma unroll
                for (int j = 0; j < 4; j++)
                    if (tx*4 + j > ty*4 + i) s[i][j] = -1e30f;
        }

        float fac[4];
        #pragma unroll
        for (int i = 0; i < 4; i++) {
            float rmax = fmaxf(fmaxf(s[i][0], s[i][1]), fmaxf(s[i][2], s[i][3]));
            #pragma unroll
            for (int off = 8; off > 0; off >>= 1)
                rmax = fmaxf(rmax, __shfl_xor_sync(0xffffffffu, rmax, off));
            float mnew = fmaxf(m_run[i], rmax);
            float rsum = 0.f;
            #pragma unroll
            for (int j = 0; j < 4; j++) {
                s[i][j] = __expf(s[i][j] - mnew);
                rsum += s[i][j];
            }
            #pragma unroll
            for (int off = 8; off > 0; off >>= 1)
                rsum += __shfl_xor_sync(0xffffffffu, rsum, off);
            fac[i] = __expf(m_run[i] - mnew);
            l_run[i] = l_run[i] * fac[i] + rsum;
            m_run[i] = mnew;
            #pragma unroll
            for (int j = 0; j < 4; j++) O[i][j] *= fac[i];
        }

        __syncthreads();

        #pragma unroll
        for (int i = 0; i < 4; i++) {
            float4 p4 = make_float4(s[i][0], s[i][1], s[i][2], s[i][3]);
            *(float4*)&KtPs[(ty*4 + i)*64 + tx*4] = p4;
        }
        __syncthreads();

        #pragma unroll 4
        for (int k = 0; k < 64; k++) {
            float4 b4 = *(const float4*)&Vs[k*64 + tx*4];
            float b[4] = {b4.x, b4.y, b4.z, b4.w};
            float a[4];
            #pragma unroll
            for (int i = 0; i < 4; i++) a[i] = KtPs[(ty*4 + i)*64 + k];
            #pragma unroll
            for (int i = 0; i < 4; i++)
                #pragma unroll
                for (int j = 0; j < 4; j++)
                    O[i][j] += a[i] * b[j];
        }
    }

    int b = bh >> 4, h = bh & 15;
    #pragma unroll
    for (int i = 0; i < 4; i++) {
        int t = qm0 + ty*4 + i;
        float inv = 1.0f / l_run[i];
        float4 o4 = make_float4(O[i][0]*inv, O[i][1]*inv, O[i][2]*inv, O[i][3]*inv);
        *(float4*)&g_ao[((size_t)b*TLEN + t)*CDIM + h*HDIM + tx*4] = o4;
    }
}

// ---------------------------------------------------------------------------
// proj GEMM reads g_ao (device symbol) — wrapped so the host never touches it
// ---------------------------------------------------------------------------
__global__ __launch_bounds__(128) void gemm_proj_entry(
    const float* __restrict__ Bm, const float* __restrict__ bias,
    float* __restrict__ out);

// Use a trampoline: instantiate proj as a separate kernel that reads g_ao.
template<int N>
__global__ __launch_bounds__(128) void gemm_tf32_proj(
    const float* __restrict__ Bm,
    const float* __restrict__ bias,
    float* __restrict__ out)
{
    // identical body via the shared template, A = g_ao
    const float* A = g_ao;
    const int K = 1024;
    __shared__ unsigned As[2][128][20];
    __shared__ unsigned Bs[2][16][136];

    const int tid  = threadIdx.x;
    const int wid  = tid >> 5;
    const int lane = tid & 31;
    const int g    = lane >> 2;
    const int q    = lane & 3;
    const int wm   = (wid >> 1) * 64;
    const int wn   = (wid & 1) * 64;
    const int m0   = blockIdx.y * 128;
    const int n0   = blockIdx.x * 128;

    const int lar = tid >> 2, lac = (tid & 3) << 2;
    const int lbr = tid >> 5, lbc = (tid & 31) << 2;

    float acc[4][8][4];
    #pragma unroll
    for (int mt = 0; mt < 4; mt++)
        #pragma unroll
        for (int nt = 0; nt < 8; nt++)
            #pragma unroll
            for (int c = 0; c < 4; c++) acc[mt][nt][c] = 0.f;

    float4 ra[4], rb[4];
    #pragma unroll
    for (int i = 0; i < 4; i++)
        ra[i] = *(const float4*)&A[(size_t)(m0 + lar + 32*i) * K + lac];
    #pragma unroll
    for (int i = 0; i < 4; i++)
        rb[i] = *(const float4*)&Bm[(size_t)(lbr + 4*i) * N + n0 + lbc];
    #pragma unroll
    for (int i = 0; i < 4; i++) {
        As[0][lar + 32*i][lac+0] = f2tf32(ra[i].x);
        As[0][lar + 32*i][lac+1] = f2tf32(ra[i].y);
        As[0][lar + 32*i][lac+2] = f2tf32(ra[i].z);
        As[0][lar + 32*i][lac+3] = f2tf32(ra[i].w);
    }
    #pragma unroll
    for (int i = 0; i < 4; i++) {
        Bs[0][lbr + 4*i][lbc+0] = f2tf32(rb[i].x);
        Bs[0][lbr + 4*i][lbc+1] = f2tf32(rb[i].y);
        Bs[0][lbr + 4*i][lbc+2] = f2tf32(rb[i].z);
        Bs[0][lbr + 4*i][lbc+3] = f2tf32(rb[i].w);
    }
    __syncthreads();

    const int NIT = K / 16;
    for (int it = 0; it < NIT; it++) {
        const int cur = it & 1;
        const int nxt = cur ^ 1;

        if (it + 1 < NIT) {
            const int kk = (it + 1) * 16;
            #pragma unroll
            for (int i = 0; i < 4; i++)
                ra[i] = *(const float4*)&A[(size_t)(m0 + lar + 32*i) * K + kk + lac];
            #pragma unroll
            for (int i = 0; i < 4; i++)
                rb[i] = *(const float4*)&Bm[(size_t)(kk + lbr + 4*i) * N + n0 + lbc];
        }

        #pragma unroll
        for (int ks = 0; ks < 2; ks++) {
            const int kq = ks * 8 + q;
            unsigned af[4][4];
            #pragma unroll
            for (int mt = 0; mt < 4; mt++) {
                const int mb = wm + mt*16 + g;
                af[mt][0] = As[cur][mb    ][kq];
                af[mt][1] = As[cur][mb + 8][kq];
                af[mt][2] = As[cur][mb    ][kq + 4];
                af[mt][3] = As[cur][mb + 8][kq + 4];
            }
            unsigned bf[8][2];
            #pragma unroll
            for (int nt = 0; nt < 8; nt++) {
                const int nb = wn + nt*8 + g;
                bf[nt][0] = Bs[cur][ks*8 + q    ][nb];
                bf[nt][1] = Bs[cur][ks*8 + q + 4][nb];
            }
            #pragma unroll
            for (int mt = 0; mt < 4; mt++)
                #pragma unroll
                for (int nt = 0; nt < 8; nt++)
                    mma_tf32(acc[mt][nt], af[mt][0], af[mt][1], af[mt][2], af[mt][3],
                             bf[nt][0], bf[nt][1]);
        }

        if (it + 1 < NIT) {
            #pragma unroll
            for (int i = 0; i < 4; i++) {
                As[nxt][lar + 32*i][lac+0] = f2tf32(ra[i].x);
                As[nxt][lar + 32*i][lac+1] = f2tf32(ra[i].y);
                As[nxt][lar + 32*i][lac+2] = f2tf32(ra[i].z);
                As[nxt][lar + 32*i][lac+3] = f2tf32(ra[i].w);
            }
            #pragma unroll
            for (int i = 0; i < 4; i++) {
                Bs[nxt][lbr + 4*i][lbc+0] = f2tf32(rb[i].x);
                Bs[nxt][lbr + 4*i][lbc+1] = f2tf32(rb[i].y);
                Bs[nxt][lbr + 4*i][lbc+2] = f2tf32(rb[i].z);
                Bs[nxt][lbr + 4*i][lbc+3] = f2tf32(rb[i].w);
            }
        }
        __syncthreads();
    }

    #pragma unroll
    for (int mt = 0; mt < 4; mt++) {
        #pragma unroll
        for (int nt = 0; nt < 8; nt++) {
            const int m = m0 + wm + mt*16 + g;
            const int n = n0 + wn + nt*8 + 2*q;
            const float2 bb = *(const float2*)&bias[n];
            #pragma unroll
            for (int r = 0; r < 2; r++) {
                const int mm = m + r*8;
                float2 v2 = make_float2(acc[mt][nt][r*2]   + bb.x,
                                        acc[mt][nt][r*2+1] + bb.y);
                *(float2*)&out[(size_t)mm * N + n] = v2;
            }
        }
    }
}

// ---------------------------------------------------------------------------
extern "C" void kernel_launch(void* const* d_in, const int* in_sizes, int n_in,
                              void* d_out, int out_size)
{
    const float* x      = (const float*)d_in[0];
    const float* w_attn = (const float*)d_in[1];
    const float* w_proj = (const float*)d_in[2];
    const float* b_proj = (const float*)d_in[3];
    float* out = (float*)d_out;

    dim3 g1(3072/128, 8192/128);   // (24, 64)
    gemm_tf32<3072, 0><<<g1, 128>>>(x, w_attn, nullptr, nullptr);

    dim3 g2(TLEN/64, BSZ*HN);      // (32, 64)
    attn_kernel<<<g2, 256>>>();

    dim3 g3(1024/128, 8192/128);   // (8, 64)
    gemm_tf32_proj<1024><<<g3, 128>>>(w_proj, b_proj, out);
}

// round 4
// speedup vs baseline: 2.5204x; 1.5118x over previous
#include <cuda_runtime.h>
#include <cstdint>

// Problem constants
#define BSZ 4
#define TLEN 2048
#define CDIM 1024
#define HN 16
#define HDIM 64

// Scratch (device globals; no allocation allowed)
__device__ float g_q[BSZ*HN*TLEN*HDIM];   // [B,H,T,HD]  (pre-scaled by 1/8)
__device__ float g_k[BSZ*HN*TLEN*HDIM];
__device__ float g_v[BSZ*HN*TLEN*HDIM];
__device__ float g_ao[BSZ*TLEN*CDIM];     // attention output [B,T,C]

// ---------------------------------------------------------------------------
// tf32 helpers
// ---------------------------------------------------------------------------
__device__ __forceinline__ unsigned f2tf32(float x) {
    unsigned y;
    asm("cvt.rna.tf32.f32 %0, %1;" : "=r"(y) : "f"(x));
    return y;
}

__device__ __forceinline__ void mma_tf32(float c[4],
                                         unsigned a0, unsigned a1, unsigned a2, unsigned a3,
                                         unsigned b0, unsigned b1) {
    asm volatile(
        "mma.sync.aligned.m16n8k8.row.col.f32.tf32.tf32.f32 "
        "{%0,%1,%2,%3}, {%4,%5,%6,%7}, {%8,%9}, {%0,%1,%2,%3};"
        : "+f"(c[0]), "+f"(c[1]), "+f"(c[2]), "+f"(c[3])
        : "r"(a0), "r"(a1), "r"(a2), "r"(a3), "r"(b0), "r"(b1));
}

// ---------------------------------------------------------------------------
// tf32 tensor-core GEMM: C[8192 x N] = A[8192 x 1024] @ B[1024 x N]
// Block 128x128xBK16, 128 threads (4 warps), warp tile 64x64.
// EPI 0: scatter into g_q (x0.125) / g_k / g_v.
// ---------------------------------------------------------------------------
template<int N, int EPI>
__global__ __launch_bounds__(128) void gemm_tf32(
    const float* __restrict__ A,
    const float* __restrict__ Bm,
    const float* __restrict__ bias,
    float* __restrict__ out)
{
    const int K = 1024;
    __shared__ unsigned As[2][128][20];
    __shared__ unsigned Bs[2][16][136];

    const int tid  = threadIdx.x;
    const int wid  = tid >> 5;
    const int lane = tid & 31;
    const int g    = lane >> 2;
    const int q    = lane & 3;
    const int wm   = (wid >> 1) * 64;
    const int wn   = (wid & 1) * 64;
    const int m0   = blockIdx.y * 128;
    const int n0   = blockIdx.x * 128;

    const int lar = tid >> 2, lac = (tid & 3) << 2;
    const int lbr = tid >> 5, lbc = (tid & 31) << 2;

    float acc[4][8][4];
    #pragma unroll
    for (int mt = 0; mt < 4; mt++)
        #pragma unroll
        for (int nt = 0; nt < 8; nt++)
            #pragma unroll
            for (int c = 0; c < 4; c++) acc[mt][nt][c] = 0.f;

    float4 ra[4], rb[4];

    #pragma unroll
    for (int i = 0; i < 4; i++)
        ra[i] = *(const float4*)&A[(size_t)(m0 + lar + 32*i) * K + lac];
    #pragma unroll
    for (int i = 0; i < 4; i++)
        rb[i] = *(const float4*)&Bm[(size_t)(lbr + 4*i) * N + n0 + lbc];
    #pragma unroll
    for (int i = 0; i < 4; i++) {
        As[0][lar + 32*i][lac+0] = f2tf32(ra[i].x);
        As[0][lar + 32*i][lac+1] = f2tf32(ra[i].y);
        As[0][lar + 32*i][lac+2] = f2tf32(ra[i].z);
        As[0][lar + 32*i][lac+3] = f2tf32(ra[i].w);
    }
    #pragma unroll
    for (int i = 0; i < 4; i++) {
        Bs[0][lbr + 4*i][lbc+0] = f2tf32(rb[i].x);
        Bs[0][lbr + 4*i][lbc+1] = f2tf32(rb[i].y);
        Bs[0][lbr + 4*i][lbc+2] = f2tf32(rb[i].z);
        Bs[0][lbr + 4*i][lbc+3] = f2tf32(rb[i].w);
    }
    __syncthreads();

    const int NIT = K / 16;
    for (int it = 0; it < NIT; it++) {
        const int cur = it & 1;
        const int nxt = cur ^ 1;

        if (it + 1 < NIT) {
            const int kk = (it + 1) * 16;
            #pragma unroll
            for (int i = 0; i < 4; i++)
                ra[i] = *(const float4*)&A[(size_t)(m0 + lar + 32*i) * K + kk + lac];
            #pragma unroll
            for (int i = 0; i < 4; i++)
                rb[i] = *(const float4*)&Bm[(size_t)(kk + lbr + 4*i) * N + n0 + lbc];
        }

        #pragma unroll
        for (int ks = 0; ks < 2; ks++) {
            const int kq = ks * 8 + q;
            unsigned af[4][4];
            #pragma unroll
            for (int mt = 0; mt < 4; mt++) {
                const int mb = wm + mt*16 + g;
                af[mt][0] = As[cur][mb    ][kq];
                af[mt][1] = As[cur][mb + 8][kq];
                af[mt][2] = As[cur][mb    ][kq + 4];
                af[mt][3] = As[cur][mb + 8][kq + 4];
            }
            unsigned bf[8][2];
            #pragma unroll
            for (int nt = 0; nt < 8; nt++) {
                const int nb = wn + nt*8 + g;
                bf[nt][0] = Bs[cur][ks*8 + q    ][nb];
                bf[nt][1] = Bs[cur][ks*8 + q + 4][nb];
            }
            #pragma unroll
            for (int mt = 0; mt < 4; mt++)
                #pragma unroll
                for (int nt = 0; nt < 8; nt++)
                    mma_tf32(acc[mt][nt], af[mt][0], af[mt][1], af[mt][2], af[mt][3],
                             bf[nt][0], bf[nt][1]);
        }

        if (it + 1 < NIT) {
            #pragma unroll
            for (int i = 0; i < 4; i++) {
                As[nxt][lar + 32*i][lac+0] = f2tf32(ra[i].x);
                As[nxt][lar + 32*i][lac+1] = f2tf32(ra[i].y);
                As[nxt][lar + 32*i][lac+2] = f2tf32(ra[i].z);
                As[nxt][lar + 32*i][lac+3] = f2tf32(ra[i].w);
            }
            #pragma unroll
            for (int i = 0; i < 4; i++) {
                Bs[nxt][lbr + 4*i][lbc+0] = f2tf32(rb[i].x);
                Bs[nxt][lbr + 4*i][lbc+1] = f2tf32(rb[i].y);
                Bs[nxt][lbr + 4*i][lbc+2] = f2tf32(rb[i].z);
                Bs[nxt][lbr + 4*i][lbc+3] = f2tf32(rb[i].w);
            }
        }
        __syncthreads();
    }

    #pragma unroll
    for (int mt = 0; mt < 4; mt++) {
        #pragma unroll
        for (int nt = 0; nt < 8; nt++) {
            const int m = m0 + wm + mt*16 + g;
            const int n = n0 + wn + nt*8 + 2*q;
            if (EPI == 0) {
                const int which = n >> 10;
                const int c = n & 1023;
                const int h = c >> 6;
                const int d = c & 63;
                float* dst = (which == 0) ? g_q : (which == 1) ? g_k : g_v;
                const float sc = (which == 0) ? 0.125f : 1.0f;
                #pragma unroll
                for (int r = 0; r < 2; r++) {
                    const int mm = m + r*8;
                    const int bb = mm >> 11;
                    const int t  = mm & 2047;
                    float2 v2 = make_float2(acc[mt][nt][r*2]   * sc,
                                            acc[mt][nt][r*2+1] * sc);
                    *(float2*)&dst[(((size_t)(bb*HN + h))*TLEN + t)*HDIM + d] = v2;
                }
            } else {
                const float2 bb = *(const float2*)&bias[n];
                #pragma unroll
                for (int r = 0; r < 2; r++) {
                    const int mm = m + r*8;
                    float2 v2 = make_float2(acc[mt][nt][r*2]   + bb.x,
                                            acc[mt][nt][r*2+1] + bb.y);
                    *(float2*)&out[(size_t)mm * N + n] = v2;
                }
            }
        }
    }
}

// ---------------------------------------------------------------------------
// Tensor-core flash attention (tf32 mma), online softmax.
// Block: 64 queries x one bh, 128 threads (4 warps), warp = 16 q-rows.
// S = Q K^T with Q hi/lo split (2 mmas) to kill Q-conversion error.
// Kt buffer reused for P (tf32) between S and PV.
// ---------------------------------------------------------------------------
__global__ __launch_bounds__(128) void attn_tc()
{
    __shared__ __align__(16) unsigned KtPs[64*72]; // Kt[d][key] s72 / Ps[q][key] s68 / Qstage s68
    __shared__ __align__(16) unsigned Vs[64*72];   // V[key][d] s72 (tf32)

    const int bh  = blockIdx.y;      // 0..63
    const int qi  = blockIdx.x;      // 0..31
    const int qm0 = qi * 64;

    const float* Qp = g_q + ((size_t)bh * TLEN + qm0) * HDIM;
    const float* Kp = g_k + (size_t)bh * TLEN * HDIM;
    const float* Vp = g_v + (size_t)bh * TLEN * HDIM;

    const int tid  = threadIdx.x;
    const int wid  = tid >> 5;
    const int lane = tid & 31;
    const int g    = lane >> 2;
    const int q    = lane & 3;
    const int wm   = wid * 16;

    // ---- stage Q (fp32) into KtPs (stride 68), then hoist A-frags to regs ----
    float* Qs = (float*)KtPs;
    for (int i = tid; i < 1024; i += 128) {
        int row = i >> 4;
        int c4  = (i & 15) << 2;
        float4 qv = *(const float4*)(Qp + row*HDIM + c4);
        Qs[row*68 + c4+0] = qv.x; Qs[row*68 + c4+1] = qv.y;
        Qs[row*68 + c4+2] = qv.z; Qs[row*68 + c4+3] = qv.w;
    }
    __syncthreads();

    unsigned qhi[8][4], qlo[8][4];
    #pragma unroll
    for (int kc = 0; kc < 8; kc++) {
        const int rows[2] = { wm + g, wm + g + 8 };
        const int cols[2] = { kc*8 + q, kc*8 + q + 4 };
        #pragma unroll
        for (int s = 0; s < 4; s++) {
            float x = Qs[rows[s & 1]*68 + cols[s >> 1]];
            unsigned hi = f2tf32(x);
            qhi[kc][s] = hi;
            qlo[kc][s] = f2tf32(x - __uint_as_float(hi));
        }
    }

    float O[8][4];
    #pragma unroll
    for (int nt = 0; nt < 8; nt++)
        #pragma unroll
        for (int c = 0; c < 4; c++) O[nt][c] = 0.f;
    float mrow[2] = { -1e30f, -1e30f };
    float lrow[2] = { 0.f, 0.f };

    for (int jt = 0; jt <= qi; jt++) {
        const int k0 = jt * 64;
        __syncthreads();   // previous PV reads / Q staging reads complete

        // K tile -> Kt[d][key] (tf32), stride 72
        for (int i = tid; i < 1024; i += 128) {
            int row = i & 63;
            int c4  = (i >> 6) << 2;
            float4 kv = *(const float4*)(Kp + (size_t)(k0 + row)*HDIM + c4);
            KtPs[(c4+0)*72 + row] = f2tf32(kv.x);
            KtPs[(c4+1)*72 + row] = f2tf32(kv.y);
            KtPs[(c4+2)*72 + row] = f2tf32(kv.z);
            KtPs[(c4+3)*72 + row] = f2tf32(kv.w);
        }
        // V tile -> Vs[key][d] (tf32), stride 72
        for (int i = tid; i < 1024; i += 128) {
            int row = i >> 4;
            int c4  = (i & 15) << 2;
            float4 vv = *(const float4*)(Vp + (size_t)(k0 + row)*HDIM + c4);
            Vs[row*72 + c4+0] = f2tf32(vv.x);
            Vs[row*72 + c4+1] = f2tf32(vv.y);
            Vs[row*72 + c4+2] = f2tf32(vv.z);
            Vs[row*72 + c4+3] = f2tf32(vv.w);
        }
        __syncthreads();

        // ---- S = Q K^T (hi + lo) ----
        float sacc[8][4];
        #pragma unroll
        for (int nt = 0; nt < 8; nt++)
            #pragma unroll
            for (int c = 0; c < 4; c++) sacc[nt][c] = 0.f;

        #pragma unroll
        for (int kc = 0; kc < 8; kc++) {
            unsigned bf[8][2];
            #pragma unroll
            for (int nt = 0; nt < 8; nt++) {
                bf[nt][0] = KtPs[(kc*8 + q    )*72 + nt*8 + g];
                bf[nt][1] = KtPs[(kc*8 + q + 4)*72 + nt*8 + g];
            }
            #pragma unroll
            for (int nt = 0; nt < 8; nt++) {
                mma_tf32(sacc[nt], qhi[kc][0], qhi[kc][1], qhi[kc][2], qhi[kc][3],
                         bf[nt][0], bf[nt][1]);
                mma_tf32(sacc[nt], qlo[kc][0], qlo[kc][1], qlo[kc][2], qlo[kc][3],
                         bf[nt][0], bf[nt][1]);
            }
        }

        // causal mask on the diagonal tile (k0 == qm0)
        if (jt == qi) {
            #pragma unroll
            for (int nt = 0; nt < 8; nt++)
                #pragma unroll
                for (int c = 0; c < 4; c++) {
                    int row = wm + g + ((c >> 1) << 3);
                    int col = nt*8 + 2*q + (c & 1);
                    if (col > row) sacc[nt][c] = -1e30f;
                }
        }

        // ---- online softmax (2 rows per thread; q-group of 4 lanes) ----
        #pragma unroll
        for (int r = 0; r < 2; r++) {
            float mx = -1e30f;
            #pragma unroll
            for (int nt = 0; nt < 8; nt++)
                mx = fmaxf(mx, fmaxf(sacc[nt][2*r], sacc[nt][2*r+1]));
            mx = fmaxf(mx, __shfl_xor_sync(0xffffffffu, mx, 1));
            mx = fmaxf(mx, __shfl_xor_sync(0xffffffffu, mx, 2));
            float mnew = fmaxf(mrow[r], mx);
            float sum = 0.f;
            #pragma unroll
            for (int nt = 0; nt < 8; nt++) {
                sacc[nt][2*r]   = __expf(sacc[nt][2*r]   - mnew);
                sacc[nt][2*r+1] = __expf(sacc[nt][2*r+1] - mnew);
                sum += sacc[nt][2*r] + sacc[nt][2*r+1];
            }
            sum += __shfl_xor_sync(0xffffffffu, sum, 1);
            sum += __shfl_xor_sync(0xffffffffu, sum, 2);
            float fac = __expf(mrow[r] - mnew);
            lrow[r] = lrow[r] * fac + sum;
            mrow[r] = mnew;
            #pragma unroll
            for (int nt = 0; nt < 8; nt++) {
                O[nt][2*r]   *= fac;
                O[nt][2*r+1] *= fac;
            }
        }

        __syncthreads();   // all warps done reading Kt

        // ---- write P (tf32) into Ps region, stride 68 ----
        #pragma unroll
        for (int nt = 0; nt < 8; nt++) {
            uint2 p0 = make_uint2(f2tf32(sacc[nt][0]), f2tf32(sacc[nt][1]));
            uint2 p1 = make_uint2(f2tf32(sacc[nt][2]), f2tf32(sacc[nt][3]));
            *(uint2*)&KtPs[(wm + g    )*68 + nt*8 + 2*q] = p0;
            *(uint2*)&KtPs[(wm + g + 8)*68 + nt*8 + 2*q] = p1;
        }
        __syncthreads();

        // ---- O += P V ----
        #pragma unroll
        for (int kc = 0; kc < 8; kc++) {
            unsigned af0 = KtPs[(wm + g    )*68 + kc*8 + q];
            unsigned af1 = KtPs[(wm + g + 8)*68 + kc*8 + q];
            unsigned af2 = KtPs[(wm + g    )*68 + kc*8 + q + 4];
            unsigned af3 = KtPs[(wm + g + 8)*68 + kc*8 + q + 4];
            #pragma unroll
            for (int nt = 0; nt < 8; nt++) {
                unsigned b0 = Vs[(kc*8 + q    )*72 + nt*8 + g];
                unsigned b1 = Vs[(kc*8 + q + 4)*72 + nt*8 + g];
                mma_tf32(O[nt], af0, af1, af2, af3, b0, b1);
            }
        }
    }

    // ---- finalize: /l, write to g_ao [B,T,C] ----
    const int b = bh >> 4, h = bh & 15;
    #pragma unroll
    for (int r = 0; r < 2; r++) {
        int t = qm0 + wm + g + 8*r;
        float inv = 1.0f / lrow[r];
        #pragma unroll
        for (int nt = 0; nt < 8; nt++) {
            float2 o2 = make_float2(O[nt][2*r] * inv, O[nt][2*r+1] * inv);
            *(float2*)&g_ao[((size_t)b*TLEN + t)*CDIM + h*HDIM + nt*8 + 2*q] = o2;
        }
    }
}

// ---------------------------------------------------------------------------
// proj GEMM reads g_ao (device symbol referenced in device code only)
// ---------------------------------------------------------------------------
template<int N>
__global__ __launch_bounds__(128) void gemm_tf32_proj(
    const float* __restrict__ Bm,
    const float* __restrict__ bias,
    float* __restrict__ out)
{
    const float* A = g_ao;
    const int K = 1024;
    __shared__ unsigned As[2][128][20];
    __shared__ unsigned Bs[2][16][136];

    const int tid  = threadIdx.x;
    const int wid  = tid >> 5;
    const int lane = tid & 31;
    const int g    = lane >> 2;
    const int q    = lane & 3;
    const int wm   = (wid >> 1) * 64;
    const int wn   = (wid & 1) * 64;
    const int m0   = blockIdx.y * 128;
    const int n0   = blockIdx.x * 128;

    const int lar = tid >> 2, lac = (tid & 3) << 2;
    const int lbr = tid >> 5, lbc = (tid & 31) << 2;

    float acc[4][8][4];
    #pragma unroll
    for (int mt = 0; mt < 4; mt++)
        #pragma unroll
        for (int nt = 0; nt < 8; nt++)
            #pragma unroll
            for (int c = 0; c < 4; c++) acc[mt][nt][c] = 0.f;

    float4 ra[4], rb[4];
    #pragma unroll
    for (int i = 0; i < 4; i++)
        ra[i] = *(const float4*)&A[(size_t)(m0 + lar + 32*i) * K + lac];
    #pragma unroll
    for (int i = 0; i < 4; i++)
        rb[i] = *(const float4*)&Bm[(size_t)(lbr + 4*i) * N + n0 + lbc];
    #pragma unroll
    for (int i = 0; i < 4; i++) {
        As[0][lar + 32*i][lac+0] = f2tf32(ra[i].x);
        As[0][lar + 32*i][lac+1] = f2tf32(ra[i].y);
        As[0][lar + 32*i][lac+2] = f2tf32(ra[i].z);
        As[0][lar + 32*i][lac+3] = f2tf32(ra[i].w);
    }
    #pragma unroll
    for (int i = 0; i < 4; i++) {
        Bs[0][lbr + 4*i][lbc+0] = f2tf32(rb[i].x);
        Bs[0][lbr + 4*i][lbc+1] = f2tf32(rb[i].y);
        Bs[0][lbr + 4*i][lbc+2] = f2tf32(rb[i].z);
        Bs[0][lbr + 4*i][lbc+3] = f2tf32(rb[i].w);
    }
    __syncthreads();

    const int NIT = K / 16;
    for (int it = 0; it < NIT; it++) {
        const int cur = it & 1;
        const int nxt = cur ^ 1;

        if (it + 1 < NIT) {
            const int kk = (it + 1) * 16;
            #pragma unroll
            for (int i = 0; i < 4; i++)
                ra[i] = *(const float4*)&A[(size_t)(m0 + lar + 32*i) * K + kk + lac];
            #pragma unroll
            for (int i = 0; i < 4; i++)
                rb[i] = *(const float4*)&Bm[(size_t)(kk + lbr + 4*i) * N + n0 + lbc];
        }

        #pragma unroll
        for (int ks = 0; ks < 2; ks++) {
            const int kq = ks * 8 + q;
            unsigned af[4][4];
            #pragma unroll
            for (int mt = 0; mt < 4; mt++) {
                const int mb = wm + mt*16 + g;
                af[mt][0] = As[cur][mb    ][kq];
                af[mt][1] = As[cur][mb + 8][kq];
                af[mt][2] = As[cur][mb    ][kq + 4];
                af[mt][3] = As[cur][mb + 8][kq + 4];
            }
            unsigned bf[8][2];
            #pragma unroll
            for (int nt = 0; nt < 8; nt++) {
                const int nb = wn + nt*8 + g;
                bf[nt][0] = Bs[cur][ks*8 + q    ][nb];
                bf[nt][1] = Bs[cur][ks*8 + q + 4][nb];
            }
            #pragma unroll
            for (int mt = 0; mt < 4; mt++)
                #pragma unroll
                for (int nt = 0; nt < 8; nt++)
                    mma_tf32(acc[mt][nt], af[mt][0], af[mt][1], af[mt][2], af[mt][3],
                             bf[nt][0], bf[nt][1]);
        }

        if (it + 1 < NIT) {
            #pragma unroll
            for (int i = 0; i < 4; i++) {
                As[nxt][lar + 32*i][lac+0] = f2tf32(ra[i].x);
                As[nxt][lar + 32*i][lac+1] = f2tf32(ra[i].y);
                As[nxt][lar + 32*i][lac+2] = f2tf32(ra[i].z);
                As[nxt][lar + 32*i][lac+3] = f2tf32(ra[i].w);
            }
            #pragma unroll
            for (int i = 0; i < 4; i++) {
                Bs[nxt][lbr + 4*i][lbc+0] = f2tf32(rb[i].x);
                Bs[nxt][lbr + 4*i][lbc+1] = f2tf32(rb[i].y);
                Bs[nxt][lbr + 4*i][lbc+2] = f2tf32(rb[i].z);
                Bs[nxt][lbr + 4*i][lbc+3] = f2tf32(rb[i].w);
            }
        }
        __syncthreads();
    }

    #pragma unroll
    for (int mt = 0; mt < 4; mt++) {
        #pragma unroll
        for (int nt = 0; nt < 8; nt++) {
            const int m = m0 + wm + mt*16 + g;
            const int n = n0 + wn + nt*8 + 2*q;
            const float2 bb = *(const float2*)&bias[n];
            #pragma unroll
            for (int r = 0; r < 2; r++) {
                const int mm = m + r*8;
                float2 v2 = make_float2(acc[mt][nt][r*2]   + bb.x,
                                        acc[mt][nt][r*2+1] + bb.y);
                *(float2*)&out[(size_t)mm * N + n] = v2;
            }
        }
    }
}

// ---------------------------------------------------------------------------
extern "C" void kernel_launch(void* const* d_in, const int* in_sizes, int n_in,
                              void* d_out, int out_size)
{
    const float* x      = (const float*)d_in[0];
    const float* w_attn = (const float*)d_in[1];
    const float* w_proj = (const float*)d_in[2];
    const float* b_proj = (const float*)d_in[3];
    float* out = (float*)d_out;

    dim3 g1(3072/128, 8192/128);   // (24, 64)
    gemm_tf32<3072, 0><<<g1, 128>>>(x, w_attn, nullptr, nullptr);

    dim3 g2(TLEN/64, BSZ*HN);      // (32, 64)
    attn_tc<<<g2, 128>>>();

    dim3 g3(1024/128, 8192/128);   // (8, 64)
    gemm_tf32_proj<1024><<<g3, 128>>>(w_proj, b_proj, out);
}

// round 6
// speedup vs baseline: 3.1080x; 1.2331x over previous
#include <cuda_runtime.h>
#include <cstdint>

// Problem constants
#define BSZ 4
#define TLEN 2048
#define CDIM 1024
#define HN 16
#define HDIM 64

// Scratch (device globals; no allocation allowed)
__device__ float g_q [BSZ*HN*TLEN*HDIM];  // [B,H,T,HD] fp32, pre-scaled by 1/8
__device__ float g_k [BSZ*HN*TLEN*HDIM];  // [B,H,HD,T] tf32-rounded (d-major!)
__device__ float g_v [BSZ*HN*TLEN*HDIM];  // [B,H,T,HD] tf32-rounded
__device__ float g_ao[BSZ*TLEN*CDIM];     // [B,T,C]    tf32-rounded
__device__ float g_xc [8192*1024];        // x       tf32-rounded
__device__ float g_wac[1024*3072];        // w_attn  tf32-rounded
__device__ float g_wpc[1024*1024];        // w_proj  tf32-rounded

// ---------------------------------------------------------------------------
// helpers
// ---------------------------------------------------------------------------
__device__ __forceinline__ unsigned f2tf32(float x) {
    unsigned y;
    asm("cvt.rna.tf32.f32 %0, %1;" : "=r"(y) : "f"(x));
    return y;
}
__device__ __forceinline__ void mma_tf32(float c[4],
                                         unsigned a0, unsigned a1, unsigned a2, unsigned a3,
                                         unsigned b0, unsigned b1) {
    asm volatile(
        "mma.sync.aligned.m16n8k8.row.col.f32.tf32.tf32.f32 "
        "{%0,%1,%2,%3}, {%4,%5,%6,%7}, {%8,%9}, {%0,%1,%2,%3};"
        : "+f"(c[0]), "+f"(c[1]), "+f"(c[2]), "+f"(c[3])
        : "r"(a0), "r"(a1), "r"(a2), "r"(a3), "r"(b0), "r"(b1));
}
__device__ __forceinline__ void cp16(float* dst, const float* src) {
    unsigned d = (unsigned)__cvta_generic_to_shared(dst);
    asm volatile("cp.async.cg.shared.global [%0], [%1], 16;" :: "r"(d), "l"(src));
}
#define CP_COMMIT() asm volatile("cp.async.commit_group;")
#define CP_WAIT(n)  asm volatile("cp.async.wait_group %0;" :: "n"(n))

// ---------------------------------------------------------------------------
// elementwise tf32 rounding of inputs
// ---------------------------------------------------------------------------
__global__ void cvt_tf32(const float* __restrict__ in, int n4, int sel)
{
    float* o = (sel == 0) ? g_xc : (sel == 1) ? g_wac : g_wpc;
    int i = blockIdx.x * blockDim.x + threadIdx.x;
    for (; i < n4; i += gridDim.x * blockDim.x) {
        float4 v = ((const float4*)in)[i];
        v.x = __uint_as_float(f2tf32(v.x));
        v.y = __uint_as_float(f2tf32(v.y));
        v.z = __uint_as_float(f2tf32(v.z));
        v.w = __uint_as_float(f2tf32(v.w));
        ((float4*)o)[i] = v;
    }
}

// ---------------------------------------------------------------------------
// tf32 GEMM, cp.async 3-stage pipeline. Inputs pre-rounded (no cvt in loop).
// C[8192 x N] = A[8192 x 1024] @ B[1024 x N].
// Block 128x128x16, 128 threads (4 warps), warp tile 64x64.
// EPI 0: scatter q(x0.125,fp32)/k(d-major,tf32)/v(tf32). EPI 1: +bias -> out.
// ---------------------------------------------------------------------------
#define AS_STRIDE 20
#define BS_STRIDE 136
#define AS_STAGE (128*AS_STRIDE)   // 2560 floats
#define BS_STAGE (16*BS_STRIDE)    // 2176 floats
#define GEMM_SMEM_FLOATS (3*(AS_STAGE + BS_STAGE))

template<int N, int EPI>
__global__ __launch_bounds__(128) void gemm_cp(
    const float* __restrict__ bias,
    float* __restrict__ out)
{
    extern __shared__ float sm[];
    float* As = sm;                    // [3][128][20]
    float* Bs = sm + 3*AS_STAGE;       // [3][16][136]

    const float* __restrict__ A  = (EPI == 0) ? g_xc  : g_ao;
    const float* __restrict__ Bm = (EPI == 0) ? g_wac : g_wpc;

    const int K = 1024;
    const int NIT = K / 16;            // 64

    const int tid  = threadIdx.x;
    const int wid  = tid >> 5;
    const int lane = tid & 31;
    const int g    = lane >> 2;
    const int q    = lane & 3;
    const int wm   = (wid >> 1) * 64;
    const int wn   = (wid & 1) * 64;
    const int m0   = blockIdx.y * 128;
    const int n0   = blockIdx.x * 128;

    const int lar = tid >> 2, lac = (tid & 3) << 2;   // A: rows lar+32i
    const int lbr = tid >> 5, lbc = (tid & 31) << 2;  // B: rows lbr+4i

    auto issue = [&](int kt) {
        const int s = kt % 3;
        #pragma unroll
        for (int i = 0; i < 4; i++)
            cp16(&As[s*AS_STAGE + (lar + 32*i)*AS_STRIDE + lac],
                 &A[(size_t)(m0 + lar + 32*i)*K + kt*16 + lac]);
        #pragma unroll
        for (int i = 0; i < 4; i++)
            cp16(&Bs[s*BS_STAGE + (lbr + 4*i)*BS_STRIDE + lbc],
                 &Bm[(size_t)(kt*16 + lbr + 4*i)*N + n0 + lbc]);
    };

    float acc[4][8][4];
    #pragma unroll
    for (int mt = 0; mt < 4; mt++)
        #pragma unroll
        for (int nt = 0; nt < 8; nt++)
            #pragma unroll
            for (int c = 0; c < 4; c++) acc[mt][nt][c] = 0.f;

    // prologue: stages 0,1
    issue(0); CP_COMMIT();
    issue(1); CP_COMMIT();
    CP_WAIT(1);
    __syncthreads();

    for (int it = 0; it < NIT; it++) {
        if (it + 2 < NIT) issue(it + 2);
        CP_COMMIT();

        const int s = it % 3;
        const float* Ac = &As[s*AS_STAGE];
        const float* Bc = &Bs[s*BS_STAGE];

        #pragma unroll
        for (int ks = 0; ks < 2; ks++) {
            const int kq = ks*8 + q;
            unsigned af[4][4];
            #pragma unroll
            for (int mt = 0; mt < 4; mt++) {
                const int mb = wm + mt*16 + g;
                af[mt][0] = __float_as_uint(Ac[(mb    )*AS_STRIDE + kq]);
                af[mt][1] = __float_as_uint(Ac[(mb + 8)*AS_STRIDE + kq]);
                af[mt][2] = __float_as_uint(Ac[(mb    )*AS_STRIDE + kq + 4]);
                af[mt][3] = __float_as_uint(Ac[(mb + 8)*AS_STRIDE + kq + 4]);
            }
            unsigned bf[8][2];
            #pragma unroll
            for (int nt = 0; nt < 8; nt++) {
                const int nb = wn + nt*8 + g;
                bf[nt][0] = __float_as_uint(Bc[(ks*8 + q    )*BS_STRIDE + nb]);
                bf[nt][1] = __float_as_uint(Bc[(ks*8 + q + 4)*BS_STRIDE + nb]);
            }
            #pragma unroll
            for (int mt = 0; mt < 4; mt++)
                #pragma unroll
                for (int nt = 0; nt < 8; nt++)
                    mma_tf32(acc[mt][nt], af[mt][0], af[mt][1], af[mt][2], af[mt][3],
                             bf[nt][0], bf[nt][1]);
        }

        CP_WAIT(1);
        __syncthreads();
    }

    // epilogue
    #pragma unroll
    for (int mt = 0; mt < 4; mt++) {
        #pragma unroll
        for (int nt = 0; nt < 8; nt++) {
            const int m = m0 + wm + mt*16 + g;
            const int n = n0 + wn + nt*8 + 2*q;
            if (EPI == 0) {
                const int which = n >> 10;
                const int c = n & 1023;
                const int h = c >> 6;
                const int d = c & 63;
                #pragma unroll
                for (int r = 0; r < 2; r++) {
                    const int mm = m + r*8;
                    const int bb = mm >> 11;
                    const int t  = mm & 2047;
                    const size_t bhb = (size_t)(bb*HN + h);
                    if (which == 0) {
                        float2 v2 = make_float2(acc[mt][nt][r*2]   * 0.125f,
                                                acc[mt][nt][r*2+1] * 0.125f);
                        *(float2*)&g_q[(bhb*TLEN + t)*HDIM + d] = v2;
                    } else if (which == 1) {
                        // K stored d-major [bh][d][t], tf32-rounded
                        g_k[(bhb*HDIM + d    )*TLEN + t] =
                            __uint_as_float(f2tf32(acc[mt][nt][r*2]));
                        g_k[(bhb*HDIM + d + 1)*TLEN + t] =
                            __uint_as_float(f2tf32(acc[mt][nt][r*2+1]));
                    } else {
                        float2 v2 = make_float2(
                            __uint_as_float(f2tf32(acc[mt][nt][r*2])),
                            __uint_as_float(f2tf32(acc[mt][nt][r*2+1])));
                        *(float2*)&g_v[(bhb*TLEN + t)*HDIM + d] = v2;
                    }
                }
            } else {
                const float2 bb = *(const float2*)&bias[n];
                #pragma unroll
                for (int r = 0; r < 2; r++) {
                    const int mm = m + r*8;
                    float2 v2 = make_float2(acc[mt][nt][r*2]   + bb.x,
                                            acc[mt][nt][r*2+1] + bb.y);
                    *(float2*)&out[(size_t)mm * N + n] = v2;
                }
            }
        }
    }
}

// ---------------------------------------------------------------------------
// Tensor-core flash attention, q-tile 128, 256 threads (8 warps), key tile 64.
// K/V double-buffered via cp.async (K is d-major in gmem -> no transpose).
// S with Q hi/lo split. P per-warp private in smem (syncwarp only).
// ---------------------------------------------------------------------------
#define KST 72
#define PST 68
#define KV_STAGE (64*KST)                       // 4608 floats
#define ATTN_SMEM_FLOATS (4*KV_STAGE + 128*PST) // 27136 floats

__global__ __launch_bounds__(256) void attn_tc()
{
    extern __shared__ float sm[];
    float* Kb = sm;                  // [2][64][72]  Kt[d][key]
    float* Vb = sm + 2*KV_STAGE;     // [2][64][72]  V[key][d]
    float* Ps = sm + 4*KV_STAGE;     // [128][68]    Q stage then P

    const int bh  = blockIdx.y;                    // 0..63
    const int qi  = (gridDim.x - 1) - blockIdx.x;  // heavy-first
    const int qm0 = qi * 128;
    const int njt = 2*qi + 2;

    const float* Qp = g_q + ((size_t)bh*TLEN + qm0) * HDIM;
    const float* Kg = g_k + (size_t)bh*HDIM*TLEN;   // [d][t]
    const float* Vg = g_v + (size_t)bh*TLEN*HDIM;   // [t][d]

    const int tid  = threadIdx.x;
    const int wid  = tid >> 5;
    const int lane = tid & 31;
    const int g    = lane >> 2;
    const int q    = lane & 3;
    const int wm   = wid * 16;

    // Full 64x64 tiles: 8 cp16 per thread (4 for K, 4 for V).
    auto issueKV = [&](int jt) {
        const int s  = jt & 1;
        const int k0 = jt * 64;
        const int row = tid >> 2;            // 0..63
        const int c0  = (tid & 3) << 2;      // 0,4,8,12
        #pragma unroll
        for (int rep = 0; rep < 4; rep++) {
            const int c4 = c0 + rep*16;      // covers 0..63
            cp16(&Kb[s*KV_STAGE + row*KST + c4],
                 &Kg[(size_t)row*TLEN + k0 + c4]);
            cp16(&Vb[s*KV_STAGE + row*KST + c4],
                 &Vg[(size_t)(k0 + row)*HDIM + c4]);
        }
    };

    // stage 0 in flight while we stage+hoist Q
    issueKV(0); CP_COMMIT();

    // stage Q fp32 into Ps (stride 68)
    for (int i = tid; i < 2048; i += 256) {
        int row = i >> 4;
        int c4  = (i & 15) << 2;
        float4 qv = *(const float4*)(Qp + (size_t)row*HDIM + c4);
        Ps[row*PST + c4+0] = qv.x; Ps[row*PST + c4+1] = qv.y;
        Ps[row*PST + c4+2] = qv.z; Ps[row*PST + c4+3] = qv.w;
    }
    __syncthreads();

    unsigned qhi[8][4], qlo[8][4];
    #pragma unroll
    for (int kc = 0; kc < 8; kc++) {
        const int rows[2] = { wm + g, wm + g + 8 };
        const int cols[2] = { kc*8 + q, kc*8 + q + 4 };
        #pragma unroll
        for (int s = 0; s < 4; s++) {
            float x = Ps[rows[s & 1]*PST + cols[s >> 1]];
            unsigned hi = f2tf32(x);
            qhi[kc][s] = hi;
            qlo[kc][s] = f2tf32(x - __uint_as_float(hi));
        }
    }

    float O[8][4];
    #pragma unroll
    for (int nt = 0; nt < 8; nt++)
        #pragma unroll
        for (int c = 0; c < 4; c++) O[nt][c] = 0.f;
    float mrow[2] = { -1e30f, -1e30f };
    float lrow[2] = { 0.f, 0.f };

    CP_WAIT(0);
    __syncthreads();

    for (int jt = 0; jt < njt; jt++) {
        if (jt + 1 < njt) issueKV(jt + 1);
        CP_COMMIT();

        const int k0  = jt * 64;
        const float* Kc = &Kb[(jt & 1)*KV_STAGE];
        const float* Vc = &Vb[(jt & 1)*KV_STAGE];

        // ---- S = Q K^T (hi + lo) ----
        float sacc[8][4];
        #pragma unroll
        for (int nt = 0; nt < 8; nt++)
            #pragma unroll
            for (int c = 0; c < 4; c++) sacc[nt][c] = 0.f;

        #pragma unroll
        for (int kc = 0; kc < 8; kc++) {
            unsigned bf[8][2];
            #pragma unroll
            for (int nt = 0; nt < 8; nt++) {
                bf[nt][0] = __float_as_uint(Kc[(kc*8 + q    )*KST + nt*8 + g]);
                bf[nt][1] = __float_as_uint(Kc[(kc*8 + q + 4)*KST + nt*8 + g]);
            }
            #pragma unroll
            for (int nt = 0; nt < 8; nt++) {
                mma_tf32(sacc[nt], qhi[kc][0], qhi[kc][1], qhi[kc][2], qhi[kc][3],
                         bf[nt][0], bf[nt][1]);
                mma_tf32(sacc[nt], qlo[kc][0], qlo[kc][1], qlo[kc][2], qlo[kc][3],
                         bf[nt][0], bf[nt][1]);
            }
        }

        // causal mask (only warps whose rows can be exceeded)
        if (k0 + 63 > qm0 + wm) {
            #pragma unroll
            for (int nt = 0; nt < 8; nt++)
                #pragma unroll
                for (int c = 0; c < 4; c++) {
                    int row = qm0 + wm + g + ((c >> 1) << 3);
                    int col = k0 + nt*8 + 2*q + (c & 1);
                    if (col > row) sacc[nt][c] = -1e30f;
                }
        }

        // ---- online softmax ----
        #pragma unroll
        for (int r = 0; r < 2; r++) {
            float mx = -1e30f;
            #pragma unroll
            for (int nt = 0; nt < 8; nt++)
                mx = fmaxf(mx, fmaxf(sacc[nt][2*r], sacc[nt][2*r+1]));
            mx = fmaxf(mx, __shfl_xor_sync(0xffffffffu, mx, 1));
            mx = fmaxf(mx, __shfl_xor_sync(0xffffffffu, mx, 2));
            float mnew = fmaxf(mrow[r], mx);
            float sum = 0.f;
            #pragma unroll
            for (int nt = 0; nt < 8; nt++) {
                sacc[nt][2*r]   = __expf(sacc[nt][2*r]   - mnew);
                sacc[nt][2*r+1] = __expf(sacc[nt][2*r+1] - mnew);
                sum += sacc[nt][2*r] + sacc[nt][2*r+1];
            }
            sum += __shfl_xor_sync(0xffffffffu, sum, 1);
            sum += __shfl_xor_sync(0xffffffffu, sum, 2);
            float fac = __expf(mrow[r] - mnew);
            lrow[r] = lrow[r] * fac + sum;
            mrow[r] = mnew;
            #pragma unroll
            for (int nt = 0; nt < 8; nt++) {
                O[nt][2*r]   *= fac;
                O[nt][2*r+1] *= fac;
            }
        }

        // ---- P (tf32) -> Ps, warp-private rows ----
        #pragma unroll
        for (int nt = 0; nt < 8; nt++) {
            uint2 p0 = make_uint2(f2tf32(sacc[nt][0]), f2tf32(sacc[nt][1]));
            uint2 p1 = make_uint2(f2tf32(sacc[nt][2]), f2tf32(sacc[nt][3]));
            *(uint2*)&Ps[(wm + g    )*PST + nt*8 + 2*q] = *(uint2*)&p0;
            *(uint2*)&Ps[(wm + g + 8)*PST + nt*8 + 2*q] = *(uint2*)&p1;
        }
        __syncwarp();

        // ---- O += P V ----
        #pragma unroll
        for (int kc = 0; kc < 8; kc++) {
            unsigned af0 = __float_as_uint(Ps[(wm + g    )*PST + kc*8 + q]);
            unsigned af1 = __float_as_uint(Ps[(wm + g + 8)*PST + kc*8 + q]);
            unsigned af2 = __float_as_uint(Ps[(wm + g    )*PST + kc*8 + q + 4]);
            unsigned af3 = __float_as_uint(Ps[(wm + g + 8)*PST + kc*8 + q + 4]);
            #pragma unroll
            for (int nt = 0; nt < 8; nt++) {
                unsigned b0 = __float_as_uint(Vc[(kc*8 + q    )*KST + nt*8 + g]);
                unsigned b1 = __float_as_uint(Vc[(kc*8 + q + 4)*KST + nt*8 + g]);
                mma_tf32(O[nt], af0, af1, af2, af3, b0, b1);
            }
        }

        CP_WAIT(0);
        __syncthreads();
    }

    // ---- finalize: /l, tf32-round, write g_ao [B,T,C] ----
    const int b = bh >> 4, h = bh & 15;
    #pragma unroll
    for (int r = 0; r < 2; r++) {
        int t = qm0 + wm + g + 8*r;
        float inv = 1.0f / lrow[r];
        #pragma unroll
        for (int nt = 0; nt < 8; nt++) {
            float2 o2 = make_float2(
                __uint_as_float(f2tf32(O[nt][2*r]   * inv)),
                __uint_as_float(f2tf32(O[nt][2*r+1] * inv)));
            *(float2*)&g_ao[((size_t)b*TLEN + t)*CDIM + h*HDIM + nt*8 + 2*q] = o2;
        }
    }
}

// ---------------------------------------------------------------------------
extern "C" void kernel_launch(void* const* d_in, const int* in_sizes, int n_in,
                              void* d_out, int out_size)
{
    const float* x      = (const float*)d_in[0];
    const float* w_attn = (const float*)d_in[1];
    const float* w_proj = (const float*)d_in[2];
    const float* b_proj = (const float*)d_in[3];
    float* out = (float*)d_out;

    const int gemm_smem = GEMM_SMEM_FLOATS * 4;   // 56832 B
    const int attn_smem = ATTN_SMEM_FLOATS * 4;   // 108544 B
    cudaFuncSetAttribute(gemm_cp<3072,0>, cudaFuncAttributeMaxDynamicSharedMemorySize, gemm_smem);
    cudaFuncSetAttribute(gemm_cp<1024,1>, cudaFuncAttributeMaxDynamicSharedMemorySize, gemm_smem);
    cudaFuncSetAttribute(attn_tc,         cudaFuncAttributeMaxDynamicSharedMemorySize, attn_smem);

    cvt_tf32<<<512, 256>>>(x,      8192*1024/4, 0);
    cvt_tf32<<<512, 256>>>(w_attn, 1024*3072/4, 1);
    cvt_tf32<<<512, 256>>>(w_proj, 1024*1024/4, 2);

    dim3 g1(3072/128, 8192/128);   // (24, 64)
    gemm_cp<3072,0><<<g1, 128, gemm_smem>>>(nullptr, nullptr);

    dim3 g2(TLEN/128, BSZ*HN);     // (16, 64)
    attn_tc<<<g2, 256, attn_smem>>>();

    dim3 g3(1024/128, 8192/128);   // (8, 64)
    gemm_cp<1024,1><<<g3, 128, gemm_smem>>>(b_proj, out);
}